// round 5
// baseline (speedup 1.0000x reference)
#include <cuda_runtime.h>
#include <cstdint>

#define T_TOK 8192
#define DIM   1024
#define HID   4096
#define NEXP  8
#define BM 128
#define BN 128
#define BK 32
#define NMPAD  136
#define MAXPAD (NMPAD * BM)

#define SA 36                       // A smem row stride (floats)
#define SB 136                      // B smem row stride (floats)
#define ASTG (BM * SA)              // 4608 floats
#define BSTG (BK * SB)              // 4352 floats

// GEMM1 fused: A + Bg + Bu per stage, 2 stages
#define STGF1 (ASTG + 2 * BSTG)     // 13312 floats
#define SMEM1 (2 * STGF1 * 4)       // 106496 bytes
// GEMM2: A + B per stage, 3 stages
#define STGF2 (ASTG + BSTG)         // 8960 floats
#define SMEM2 (3 * STGF2 * 4)       // 107520 bytes

// ---------------- scratch ----------------
__device__ float g_hg[(size_t)MAXPAD * HID];
__device__ int   g_perm[MAXPAD];
__device__ float g_permw[MAXPAD];
__device__ int   g_offpad[NEXP + 1];
__device__ int   g_cnt[NEXP];
__device__ int   g_cursor[NEXP];
__device__ float g_probsum[NEXP];
__device__ int   g_topi[T_TOK * 2];
__device__ float g_topw[T_TOK * 2];

// ---------------- helpers ----------------
__device__ __forceinline__ uint32_t smem_u32(const void* p) {
    uint32_t a;
    asm("{ .reg .u64 t; cvta.to.shared.u64 t, %1; cvt.u32.u64 %0, t; }"
        : "=r"(a) : "l"(p));
    return a;
}
__device__ __forceinline__ float frna(float x) {
    uint32_t o; asm("cvt.rna.tf32.f32 %0, %1;" : "=r"(o) : "f"(x));
    return __uint_as_float(o);
}
__device__ __forceinline__ uint32_t frna_u(uint32_t x) {
    uint32_t o; asm("cvt.rna.tf32.f32 %0, %1;" : "=r"(o) : "f"(__uint_as_float(x)));
    return o;
}
__device__ __forceinline__ void cp16(uint32_t d, const float* s, uint32_t sz) {
    asm volatile("cp.async.cg.shared.global [%0], [%1], 16, %2;"
                 :: "r"(d), "l"(s), "r"(sz));
}
#define CP_COMMIT() asm volatile("cp.async.commit_group;" ::: "memory")
#define CP_WAIT1()  asm volatile("cp.async.wait_group 1;" ::: "memory")
#define CP_WAIT2()  asm volatile("cp.async.wait_group 2;" ::: "memory")

__device__ __forceinline__ void mma_tf32(float* c, const uint32_t* a,
                                         const uint32_t* b) {
    asm volatile(
        "mma.sync.aligned.m16n8k8.row.col.f32.tf32.tf32.f32 "
        "{%0,%1,%2,%3}, {%4,%5,%6,%7}, {%8,%9}, {%0,%1,%2,%3};"
        : "+f"(c[0]), "+f"(c[1]), "+f"(c[2]), "+f"(c[3])
        : "r"(a[0]), "r"(a[1]), "r"(a[2]), "r"(a[3]), "r"(b[0]), "r"(b[1]));
}

// ---------------- small kernels ----------------
__global__ void k_init() {
    int i = blockIdx.x * blockDim.x + threadIdx.x;
    if (i < NEXP) { g_cnt[i] = 0; g_cursor[i] = 0; g_probsum[i] = 0.f; }
    if (i < MAXPAD) g_perm[i] = -1;
}

__global__ void k_zero_out(float4* out, int n4) {
    float4 z = make_float4(0.f, 0.f, 0.f, 0.f);
    for (int i = blockIdx.x * blockDim.x + threadIdx.x; i < n4;
         i += gridDim.x * blockDim.x)
        out[i] = z;
}

__global__ void k_gate(const float* __restrict__ x, const float* __restrict__ gw) {
    int gwarp = (blockIdx.x * blockDim.x + threadIdx.x) >> 5;
    int lane  = threadIdx.x & 31;
    if (gwarp >= T_TOK) return;
    const float* xr = x + (size_t)gwarp * DIM;

    float acc[NEXP];
#pragma unroll
    for (int e = 0; e < NEXP; e++) acc[e] = 0.f;
    for (int i = lane; i < DIM; i += 32) {
        float xv = xr[i];
        float4 g0 = *(const float4*)(gw + (size_t)i * NEXP);
        float4 g1 = *(const float4*)(gw + (size_t)i * NEXP + 4);
        acc[0] += xv * g0.x; acc[1] += xv * g0.y;
        acc[2] += xv * g0.z; acc[3] += xv * g0.w;
        acc[4] += xv * g1.x; acc[5] += xv * g1.y;
        acc[6] += xv * g1.z; acc[7] += xv * g1.w;
    }
#pragma unroll
    for (int off = 16; off > 0; off >>= 1)
#pragma unroll
        for (int e = 0; e < NEXP; e++)
            acc[e] += __shfl_xor_sync(0xffffffffu, acc[e], off);

    float mx = acc[0];
#pragma unroll
    for (int e = 1; e < NEXP; e++) mx = fmaxf(mx, acc[e]);
    float p[NEXP], s = 0.f;
#pragma unroll
    for (int e = 0; e < NEXP; e++) { p[e] = __expf(acc[e] - mx); s += p[e]; }
    float inv = 1.f / s;
    if (lane < NEXP) atomicAdd(&g_probsum[lane], p[lane] * inv);

    if (lane == 0) {
        int i0 = 0;
#pragma unroll
        for (int e = 1; e < NEXP; e++) if (acc[e] > acc[i0]) i0 = e;
        int i1 = (i0 == 0) ? 1 : 0;
#pragma unroll
        for (int e = 0; e < NEXP; e++)
            if (e != i0 && acc[e] > acc[i1]) i1 = e;
        float m2 = fmaxf(acc[i0], acc[i1]);
        float e0 = __expf(acc[i0] - m2), e1 = __expf(acc[i1] - m2);
        float inv2 = 1.f / (e0 + e1);
        g_topi[2 * gwarp]     = i0; g_topw[2 * gwarp]     = e0 * inv2;
        g_topi[2 * gwarp + 1] = i1; g_topw[2 * gwarp + 1] = e1 * inv2;
        atomicAdd(&g_cnt[i0], 1);
        atomicAdd(&g_cnt[i1], 1);
    }
}

__global__ void k_offsets(float* __restrict__ out) {
    if (threadIdx.x != 0 || blockIdx.x != 0) return;
    int off = 0;
    for (int e = 0; e < NEXP; e++) {
        g_offpad[e] = off;
        off += ((g_cnt[e] + BM - 1) / BM) * BM;
    }
    g_offpad[NEXP] = off;
    float loss = 0.f;
    const float invT = 1.f / (float)T_TOK;
    for (int e = 0; e < NEXP; e++) {
        float m = g_probsum[e] * invT;
        out[(size_t)T_TOK * DIM + 1 + e] = m;
        loss += m * m;
    }
    out[(size_t)T_TOK * DIM] = (float)NEXP * loss;
}

__global__ void k_scatter() {
    int t = blockIdx.x * blockDim.x + threadIdx.x;
    if (t >= 2 * T_TOK) return;
    int e = g_topi[t];
    int pos = g_offpad[e] + atomicAdd(&g_cursor[e], 1);
    g_perm[pos]  = t >> 1;
    g_permw[pos] = g_topw[t];
}

// ---------------- GEMM1 fused: gate & up + silu epilogue ----------------
// C = silu(A@Wg) * (A@Wu), A gathered rows of x. 128x128 tile, both B's.
__global__ __launch_bounds__(256) void k_gemm1f(const float* __restrict__ x,
                                                const float* __restrict__ w_gate,
                                                const float* __restrict__ w_up) {
    extern __shared__ float sm[];
    int total = g_offpad[NEXP];
    int mbase = blockIdx.y * BM;
    if (mbase >= total) return;
    int e = 0;
#pragma unroll
    for (int i = 0; i < NEXP; i++) if (mbase >= g_offpad[i + 1]) e = i + 1;

    const float* Wg = w_gate + (size_t)e * DIM * HID;
    const float* Wu = w_up   + (size_t)e * DIM * HID;
    int ncol = blockIdx.x * BN;

    int tid = threadIdx.x;
    uint32_t smb = smem_u32(sm);

    // A: 4 chunks/thread (gathered token rows of x, raw f32)
    int arow0 = tid >> 3, akf = (tid & 7) * 4;
    uint32_t adst[4]; const float* asrc[4]; uint32_t asz[4];
#pragma unroll
    for (int p = 0; p < 4; p++) {
        int row = arow0 + p * 32;
        adst[p] = (uint32_t)(row * SA + akf) * 4;
        int tok = g_perm[mbase + row];
        asrc[p] = x + ((tok >= 0) ? (size_t)tok * DIM : 0) + akf;
        asz[p]  = (tok >= 0) ? 16u : 0u;
    }
    // B: 4 chunks/thread per matrix
    int bkr0 = tid >> 5, bnf = (tid & 31) * 4;
    uint32_t bgdst[4], budst[4]; const float *bgsrc[4], *busrc[4];
#pragma unroll
    for (int p = 0; p < 4; p++) {
        int kr = bkr0 + p * 8;
        bgdst[p] = (uint32_t)(ASTG + kr * SB + bnf) * 4;
        budst[p] = (uint32_t)(ASTG + BSTG + kr * SB + bnf) * 4;
        bgsrc[p] = Wg + (size_t)kr * HID + ncol + bnf;
        busrc[p] = Wu + (size_t)kr * HID + ncol + bnf;
    }

    int lane = tid & 31, gid = lane >> 2, tig = lane & 3;
    int wm = (tid >> 5) & 3, wn = tid >> 7;
    int r0 = wm * 32 + gid, cb = wn * 64 + gid;

    float accg[2][8][4], accu[2][8][4];
#pragma unroll
    for (int mt = 0; mt < 2; mt++)
#pragma unroll
        for (int nt = 0; nt < 8; nt++)
#pragma unroll
            for (int q = 0; q < 4; q++) { accg[mt][nt][q] = 0.f; accu[mt][nt][q] = 0.f; }

    const int NT = DIM / BK;             // 32
#pragma unroll
    for (int t = 0; t < 2; t++) {        // prologue: stages 0,1
        uint32_t base = smb + t * (STGF1 * 4);
        int k0 = t * BK;
#pragma unroll
        for (int p = 0; p < 4; p++) cp16(base + adst[p], asrc[p] + k0, asz[p]);
#pragma unroll
        for (int p = 0; p < 4; p++)
            cp16(base + bgdst[p], bgsrc[p] + (size_t)k0 * HID, 16);
#pragma unroll
        for (int p = 0; p < 4; p++)
            cp16(base + budst[p], busrc[p] + (size_t)k0 * HID, 16);
        CP_COMMIT();
    }

    for (int i = 0; i < NT; i++) {
        CP_WAIT1();
        __syncthreads();
        const uint32_t* Au = (const uint32_t*)(sm + (i & 1) * STGF1);
        const uint32_t* Bg = Au + ASTG;
        const uint32_t* Bu = Bg + BSTG;
#pragma unroll
        for (int ks = 0; ks < 4; ks++) {
            int k = ks * 8;
            uint32_t a[2][4], b[8][2];
#pragma unroll
            for (int mt = 0; mt < 2; mt++) {
                int rr = r0 + mt * 16;
                a[mt][0] = frna_u(Au[rr * SA + k + tig]);
                a[mt][1] = frna_u(Au[(rr + 8) * SA + k + tig]);
                a[mt][2] = frna_u(Au[rr * SA + k + 4 + tig]);
                a[mt][3] = frna_u(Au[(rr + 8) * SA + k + 4 + tig]);
            }
#pragma unroll
            for (int nt = 0; nt < 8; nt++) {
                int cc = cb + nt * 8;
                b[nt][0] = frna_u(Bg[(k + tig) * SB + cc]);
                b[nt][1] = frna_u(Bg[(k + tig + 4) * SB + cc]);
            }
#pragma unroll
            for (int mt = 0; mt < 2; mt++)
#pragma unroll
                for (int nt = 0; nt < 8; nt++)
                    mma_tf32(accg[mt][nt], a[mt], b[nt]);
#pragma unroll
            for (int nt = 0; nt < 8; nt++) {
                int cc = cb + nt * 8;
                b[nt][0] = frna_u(Bu[(k + tig) * SB + cc]);
                b[nt][1] = frna_u(Bu[(k + tig + 4) * SB + cc]);
            }
#pragma unroll
            for (int mt = 0; mt < 2; mt++)
#pragma unroll
                for (int nt = 0; nt < 8; nt++)
                    mma_tf32(accu[mt][nt], a[mt], b[nt]);
        }
        __syncthreads();
        int t = i + 2;
        if (t < NT) {
            uint32_t base = smb + (t & 1) * (STGF1 * 4);
            int k0 = t * BK;
#pragma unroll
            for (int p = 0; p < 4; p++) cp16(base + adst[p], asrc[p] + k0, asz[p]);
#pragma unroll
            for (int p = 0; p < 4; p++)
                cp16(base + bgdst[p], bgsrc[p] + (size_t)k0 * HID, 16);
#pragma unroll
            for (int p = 0; p < 4; p++)
                cp16(base + budst[p], busrc[p] + (size_t)k0 * HID, 16);
        }
        CP_COMMIT();
    }

    // epilogue: h = frna(silu(g) * u), write g_hg only
#pragma unroll
    for (int mt = 0; mt < 2; mt++) {
        int r = mbase + wm * 32 + mt * 16 + gid;
#pragma unroll
        for (int nt = 0; nt < 8; nt++) {
            int c = ncol + wn * 64 + nt * 8 + 2 * tig;
            float g0 = accg[mt][nt][0], g1 = accg[mt][nt][1];
            float g2 = accg[mt][nt][2], g3 = accg[mt][nt][3];
            float h0 = frna(g0 * (1.f / (1.f + __expf(-g0))) * accu[mt][nt][0]);
            float h1 = frna(g1 * (1.f / (1.f + __expf(-g1))) * accu[mt][nt][1]);
            float h2 = frna(g2 * (1.f / (1.f + __expf(-g2))) * accu[mt][nt][2]);
            float h3 = frna(g3 * (1.f / (1.f + __expf(-g3))) * accu[mt][nt][3]);
            *(float2*)&g_hg[(size_t)r * HID + c]       = make_float2(h0, h1);
            *(float2*)&g_hg[(size_t)(r + 8) * HID + c] = make_float2(h2, h3);
        }
    }
}

// ---------------- GEMM2: [Mpad,4096] x [4096,1024], atomic epilogue -------------
__global__ __launch_bounds__(256) void k_gemm2_mma(const float* __restrict__ w_down,
                                                   float* __restrict__ out) {
    extern __shared__ float sm[];
    int total = g_offpad[NEXP];
    int mbase = blockIdx.y * BM;
    if (mbase >= total) return;
    int e = 0;
#pragma unroll
    for (int i = 0; i < NEXP; i++) if (mbase >= g_offpad[i + 1]) e = i + 1;

    const float* W = w_down + (size_t)e * HID * DIM;
    int ncol = blockIdx.x * BN;

    int tid = threadIdx.x;
    uint32_t smb = smem_u32(sm);

    int arow0 = tid >> 3, akf = (tid & 7) * 4;
    uint32_t adst[4]; const float* asrc[4];
#pragma unroll
    for (int p = 0; p < 4; p++) {
        int row = arow0 + p * 32;
        adst[p] = (uint32_t)(row * SA + akf) * 4;
        asrc[p] = g_hg + (size_t)(mbase + row) * HID + akf;
    }
    int bkr0 = tid >> 5, bnf = (tid & 31) * 4;
    uint32_t bdst[4]; const float* bsrc[4];
#pragma unroll
    for (int p = 0; p < 4; p++) {
        int kr = bkr0 + p * 8;
        bdst[p] = (uint32_t)(ASTG + kr * SB + bnf) * 4;
        bsrc[p] = W + (size_t)kr * DIM + ncol + bnf;
    }

    int lane = tid & 31, gid = lane >> 2, tig = lane & 3;
    int wm = (tid >> 5) & 3, wn = tid >> 7;
    int r0 = wm * 32 + gid, cb = wn * 64 + gid;

    float acc[2][8][4];
#pragma unroll
    for (int mt = 0; mt < 2; mt++)
#pragma unroll
        for (int nt = 0; nt < 8; nt++)
#pragma unroll
            for (int q = 0; q < 4; q++) acc[mt][nt][q] = 0.f;

    const int NT = HID / BK;            // 128
#pragma unroll
    for (int t = 0; t < 3; t++) {
        uint32_t base = smb + t * (STGF2 * 4);
        int k0 = t * BK;
#pragma unroll
        for (int p = 0; p < 4; p++) cp16(base + adst[p], asrc[p] + k0, 16);
#pragma unroll
        for (int p = 0; p < 4; p++)
            cp16(base + bdst[p], bsrc[p] + (size_t)k0 * DIM, 16);
        CP_COMMIT();
    }

    for (int i = 0; i < NT; i++) {
        CP_WAIT2();
        __syncthreads();
        const uint32_t* Au = (const uint32_t*)(sm + (i % 3) * STGF2);
        const uint32_t* Bu = Au + ASTG;
#pragma unroll
        for (int ks = 0; ks < 4; ks++) {
            int k = ks * 8;
            uint32_t a[2][4], b[8][2];
#pragma unroll
            for (int mt = 0; mt < 2; mt++) {
                int rr = r0 + mt * 16;
                a[mt][0] = Au[rr * SA + k + tig];
                a[mt][1] = Au[(rr + 8) * SA + k + tig];
                a[mt][2] = Au[rr * SA + k + 4 + tig];
                a[mt][3] = Au[(rr + 8) * SA + k + 4 + tig];
            }
#pragma unroll
            for (int nt = 0; nt < 8; nt++) {
                int cc = cb + nt * 8;
                b[nt][0] = frna_u(Bu[(k + tig) * SB + cc]);
                b[nt][1] = frna_u(Bu[(k + tig + 4) * SB + cc]);
            }
#pragma unroll
            for (int mt = 0; mt < 2; mt++)
#pragma unroll
                for (int nt = 0; nt < 8; nt++)
                    mma_tf32(acc[mt][nt], a[mt], b[nt]);
        }
        __syncthreads();
        int t = i + 3;
        if (t < NT) {
            uint32_t base = smb + (t % 3) * (STGF2 * 4);
            int k0 = t * BK;
#pragma unroll
            for (int p = 0; p < 4; p++) cp16(base + adst[p], asrc[p] + k0, 16);
#pragma unroll
            for (int p = 0; p < 4; p++)
                cp16(base + bdst[p], bsrc[p] + (size_t)k0 * DIM, 16);
        }
        CP_COMMIT();
    }

#pragma unroll
    for (int mt = 0; mt < 2; mt++) {
        int slot = mbase + wm * 32 + mt * 16 + gid;
        int tok0 = g_perm[slot],     tok1 = g_perm[slot + 8];
        float w0 = g_permw[slot],    w1 = g_permw[slot + 8];
#pragma unroll
        for (int nt = 0; nt < 8; nt++) {
            int c = ncol + wn * 64 + nt * 8 + 2 * tig;
            if (tok0 >= 0) {
                float* op = out + (size_t)tok0 * DIM + c;
                atomicAdd(op,     w0 * acc[mt][nt][0]);
                atomicAdd(op + 1, w0 * acc[mt][nt][1]);
            }
            if (tok1 >= 0) {
                float* op = out + (size_t)tok1 * DIM + c;
                atomicAdd(op,     w1 * acc[mt][nt][2]);
                atomicAdd(op + 1, w1 * acc[mt][nt][3]);
            }
        }
    }
}

// ---------------- launch ----------------
extern "C" void kernel_launch(void* const* d_in, const int* in_sizes, int n_in,
                              void* d_out, int out_size) {
    const float* x      = (const float*)d_in[0];
    const float* gate_w = (const float*)d_in[1];
    const float* w_gate = (const float*)d_in[2];
    const float* w_up   = (const float*)d_in[3];
    const float* w_down = (const float*)d_in[4];
    float* out = (float*)d_out;

    cudaFuncSetAttribute(k_gemm1f, cudaFuncAttributeMaxDynamicSharedMemorySize,
                         SMEM1);
    cudaFuncSetAttribute(k_gemm2_mma, cudaFuncAttributeMaxDynamicSharedMemorySize,
                         SMEM2);

    k_init<<<MAXPAD / 256, 256>>>();
    k_zero_out<<<2048, 256>>>((float4*)out, (T_TOK * DIM) / 4);
    k_gate<<<T_TOK / 8, 256>>>(x, gate_w);
    k_offsets<<<1, 32>>>(out);
    k_scatter<<<(2 * T_TOK) / 256, 256>>>();

    k_gemm1f<<<dim3(HID / BN, NMPAD), 256, SMEM1>>>(x, w_gate, w_up);
    k_gemm2_mma<<<dim3(DIM / BN, NMPAD), 256, SMEM2>>>(w_down, out);
}

// round 6
// speedup vs baseline: 1.0447x; 1.0447x over previous
#include <cuda_runtime.h>
#include <cstdint>

#define T_TOK 8192
#define DIM   1024
#define HID   4096
#define NEXP  8
#define BM 128
#define BN 128
#define BK 32
#define NMPAD  136
#define MAXPAD (NMPAD * BM)

#define SA 36                       // A smem row stride (floats)
#define SB 136                      // B smem row stride (floats)
#define ASTG (BM * SA)              // 4608 floats
#define BSTG (BK * SB)              // 4352 floats
#define STGF (ASTG + BSTG)          // 8960 floats per stage
#define STGB (STGF * 4)             // 35840 bytes
#define SMEM_DYN (3 * STGB)         // 107520 bytes -> 2 CTAs/SM

// ---------------- scratch ----------------
__device__ float g_hg[(size_t)MAXPAD * HID];
__device__ float g_hu[(size_t)MAXPAD * HID];
__device__ int   g_perm[MAXPAD];
__device__ float g_permw[MAXPAD];
__device__ int   g_offpad[NEXP + 1];
__device__ int   g_cnt[NEXP];
__device__ int   g_cursor[NEXP];
__device__ float g_probsum[NEXP];
__device__ int   g_topi[T_TOK * 2];
__device__ float g_topw[T_TOK * 2];

// ---------------- helpers ----------------
__device__ __forceinline__ uint32_t smem_u32(const void* p) {
    uint32_t a;
    asm("{ .reg .u64 t; cvta.to.shared.u64 t, %1; cvt.u32.u64 %0, t; }"
        : "=r"(a) : "l"(p));
    return a;
}
__device__ __forceinline__ float frna(float x) {
    uint32_t o; asm("cvt.rna.tf32.f32 %0, %1;" : "=r"(o) : "f"(x));
    return __uint_as_float(o);
}
// RNA-to-tf32 via integer add: HMMA truncates to top 19 bits; bits+0x1000 then
// truncation == round-to-nearest-ties-away == cvt.rna.tf32. Full-rate ALU op.
__device__ __forceinline__ uint32_t rna13(uint32_t x) { return x + 0x1000u; }

__device__ __forceinline__ void cp16(uint32_t d, const float* s, uint32_t sz) {
    asm volatile("cp.async.cg.shared.global [%0], [%1], 16, %2;"
                 :: "r"(d), "l"(s), "r"(sz));
}
#define CP_COMMIT() asm volatile("cp.async.commit_group;" ::: "memory")
#define CP_WAIT2()  asm volatile("cp.async.wait_group 2;" ::: "memory")

__device__ __forceinline__ void mma_tf32(float* c, const uint32_t* a,
                                         const uint32_t* b) {
    asm volatile(
        "mma.sync.aligned.m16n8k8.row.col.f32.tf32.tf32.f32 "
        "{%0,%1,%2,%3}, {%4,%5,%6,%7}, {%8,%9}, {%0,%1,%2,%3};"
        : "+f"(c[0]), "+f"(c[1]), "+f"(c[2]), "+f"(c[3])
        : "r"(a[0]), "r"(a[1]), "r"(a[2]), "r"(a[3]), "r"(b[0]), "r"(b[1]));
}

// ---------------- small kernels ----------------
__global__ void k_init() {
    int i = blockIdx.x * blockDim.x + threadIdx.x;
    if (i < NEXP) { g_cnt[i] = 0; g_cursor[i] = 0; g_probsum[i] = 0.f; }
    if (i < MAXPAD) g_perm[i] = -1;
}

__global__ void k_zero_out(float4* out, int n4) {
    float4 z = make_float4(0.f, 0.f, 0.f, 0.f);
    for (int i = blockIdx.x * blockDim.x + threadIdx.x; i < n4;
         i += gridDim.x * blockDim.x)
        out[i] = z;
}

__global__ void k_gate(const float* __restrict__ x, const float* __restrict__ gw) {
    int gwarp = (blockIdx.x * blockDim.x + threadIdx.x) >> 5;
    int lane  = threadIdx.x & 31;
    if (gwarp >= T_TOK) return;
    const float* xr = x + (size_t)gwarp * DIM;

    float acc[NEXP];
#pragma unroll
    for (int e = 0; e < NEXP; e++) acc[e] = 0.f;
    for (int i = lane; i < DIM; i += 32) {
        float xv = xr[i];
        float4 g0 = *(const float4*)(gw + (size_t)i * NEXP);
        float4 g1 = *(const float4*)(gw + (size_t)i * NEXP + 4);
        acc[0] += xv * g0.x; acc[1] += xv * g0.y;
        acc[2] += xv * g0.z; acc[3] += xv * g0.w;
        acc[4] += xv * g1.x; acc[5] += xv * g1.y;
        acc[6] += xv * g1.z; acc[7] += xv * g1.w;
    }
#pragma unroll
    for (int off = 16; off > 0; off >>= 1)
#pragma unroll
        for (int e = 0; e < NEXP; e++)
            acc[e] += __shfl_xor_sync(0xffffffffu, acc[e], off);

    float mx = acc[0];
#pragma unroll
    for (int e = 1; e < NEXP; e++) mx = fmaxf(mx, acc[e]);
    float p[NEXP], s = 0.f;
#pragma unroll
    for (int e = 0; e < NEXP; e++) { p[e] = __expf(acc[e] - mx); s += p[e]; }
    float inv = 1.f / s;
    if (lane < NEXP) atomicAdd(&g_probsum[lane], p[lane] * inv);

    if (lane == 0) {
        int i0 = 0;
#pragma unroll
        for (int e = 1; e < NEXP; e++) if (acc[e] > acc[i0]) i0 = e;
        int i1 = (i0 == 0) ? 1 : 0;
#pragma unroll
        for (int e = 0; e < NEXP; e++)
            if (e != i0 && acc[e] > acc[i1]) i1 = e;
        float m2 = fmaxf(acc[i0], acc[i1]);
        float e0 = __expf(acc[i0] - m2), e1 = __expf(acc[i1] - m2);
        float inv2 = 1.f / (e0 + e1);
        g_topi[2 * gwarp]     = i0; g_topw[2 * gwarp]     = e0 * inv2;
        g_topi[2 * gwarp + 1] = i1; g_topw[2 * gwarp + 1] = e1 * inv2;
        atomicAdd(&g_cnt[i0], 1);
        atomicAdd(&g_cnt[i1], 1);
    }
}

__global__ void k_offsets(float* __restrict__ out) {
    if (threadIdx.x != 0 || blockIdx.x != 0) return;
    int off = 0;
    for (int e = 0; e < NEXP; e++) {
        g_offpad[e] = off;
        off += ((g_cnt[e] + BM - 1) / BM) * BM;
    }
    g_offpad[NEXP] = off;
    float loss = 0.f;
    const float invT = 1.f / (float)T_TOK;
    for (int e = 0; e < NEXP; e++) {
        float m = g_probsum[e] * invT;
        out[(size_t)T_TOK * DIM + 1 + e] = m;
        loss += m * m;
    }
    out[(size_t)T_TOK * DIM] = (float)NEXP * loss;
}

__global__ void k_scatter() {
    int t = blockIdx.x * blockDim.x + threadIdx.x;
    if (t >= 2 * T_TOK) return;
    int e = g_topi[t];
    int pos = g_offpad[e] + atomicAdd(&g_cursor[e], 1);
    g_perm[pos]  = t >> 1;
    g_permw[pos] = g_topw[t];
}

// h = frna(silu(g)*u) -> g_hg (pre-rounded so GEMM2 A frags need no rounding)
__global__ void k_silu() {
    size_t total = (size_t)g_offpad[NEXP] * HID;
    size_t stride = (size_t)gridDim.x * blockDim.x * 4;
    for (size_t idx = ((size_t)blockIdx.x * blockDim.x + threadIdx.x) * 4;
         idx < total; idx += stride) {
        float4 a = *(float4*)&g_hg[idx];
        float4 b = *(float4*)&g_hu[idx];
        float4 r;
        r.x = frna(a.x * (1.f / (1.f + __expf(-a.x))) * b.x);
        r.y = frna(a.y * (1.f / (1.f + __expf(-a.y))) * b.y);
        r.z = frna(a.z * (1.f / (1.f + __expf(-a.z))) * b.z);
        r.w = frna(a.w * (1.f / (1.f + __expf(-a.w))) * b.w);
        *(float4*)&g_hg[idx] = r;
    }
}

// ---------------- GEMM1: [Mpad,1024] x [1024,4096] for gate & up ----------------
__global__ __launch_bounds__(256) void k_gemm1_mma(const float* __restrict__ x,
                                                   const float* __restrict__ w_gate,
                                                   const float* __restrict__ w_up) {
    extern __shared__ float sm[];
    int total = g_offpad[NEXP];
    int mbase = blockIdx.y * BM;
    if (mbase >= total) return;
    int e = 0;
#pragma unroll
    for (int i = 0; i < NEXP; i++) if (mbase >= g_offpad[i + 1]) e = i + 1;

    int bx = blockIdx.x;                 // 0..63 : [gate 0-31 | up 32-63]
    const float* W = ((bx < 32) ? w_gate : w_up) + (size_t)e * DIM * HID;
    float* C = (bx < 32) ? g_hg : g_hu;
    int ncol = (bx & 31) * BN;

    int tid = threadIdx.x;
    uint32_t smb = smem_u32(sm);

    int arow0 = tid >> 3, akf = (tid & 7) * 4;
    uint32_t adst[4]; const float* asrc[4]; uint32_t asz[4];
#pragma unroll
    for (int p = 0; p < 4; p++) {
        int row = arow0 + p * 32;
        adst[p] = (uint32_t)(row * SA + akf) * 4;
        int tok = g_perm[mbase + row];
        asrc[p] = x + ((tok >= 0) ? (size_t)tok * DIM : 0) + akf;
        asz[p]  = (tok >= 0) ? 16u : 0u;
    }
    int bkr0 = tid >> 5, bnf = (tid & 31) * 4;
    uint32_t bdst[4]; const float* bsrc[4];
#pragma unroll
    for (int p = 0; p < 4; p++) {
        int kr = bkr0 + p * 8;
        bdst[p] = (uint32_t)(ASTG + kr * SB + bnf) * 4;
        bsrc[p] = W + (size_t)kr * HID + ncol + bnf;
    }

    int lane = tid & 31, gid = lane >> 2, tig = lane & 3;
    int wm = (tid >> 5) & 3, wn = tid >> 7;
    int r0 = wm * 32 + gid, cb = wn * 64 + gid;

    float acc[2][8][4];
#pragma unroll
    for (int mt = 0; mt < 2; mt++)
#pragma unroll
        for (int nt = 0; nt < 8; nt++)
#pragma unroll
            for (int q = 0; q < 4; q++) acc[mt][nt][q] = 0.f;

    const int NT = DIM / BK;             // 32
#pragma unroll
    for (int t = 0; t < 3; t++) {
        uint32_t base = smb + t * STGB;
        int k0 = t * BK;
#pragma unroll
        for (int p = 0; p < 4; p++) cp16(base + adst[p], asrc[p] + k0, asz[p]);
#pragma unroll
        for (int p = 0; p < 4; p++)
            cp16(base + bdst[p], bsrc[p] + (size_t)k0 * HID, 16);
        CP_COMMIT();
    }

    for (int i = 0; i < NT; i++) {
        CP_WAIT2();
        __syncthreads();
        const uint32_t* Au = (const uint32_t*)(sm + (i % 3) * STGF);
        const uint32_t* Bu = Au + ASTG;
#pragma unroll
        for (int ks = 0; ks < 4; ks++) {
            int k = ks * 8;
            uint32_t a[2][4], b[8][2];
#pragma unroll
            for (int mt = 0; mt < 2; mt++) {
                int rr = r0 + mt * 16;
                a[mt][0] = rna13(Au[rr * SA + k + tig]);
                a[mt][1] = rna13(Au[(rr + 8) * SA + k + tig]);
                a[mt][2] = rna13(Au[rr * SA + k + 4 + tig]);
                a[mt][3] = rna13(Au[(rr + 8) * SA + k + 4 + tig]);
            }
#pragma unroll
            for (int nt = 0; nt < 8; nt++) {
                int cc = cb + nt * 8;
                b[nt][0] = rna13(Bu[(k + tig) * SB + cc]);
                b[nt][1] = rna13(Bu[(k + tig + 4) * SB + cc]);
            }
#pragma unroll
            for (int mt = 0; mt < 2; mt++)
#pragma unroll
                for (int nt = 0; nt < 8; nt++)
                    mma_tf32(acc[mt][nt], a[mt], b[nt]);
        }
        __syncthreads();
        int t = i + 3;
        if (t < NT) {
            uint32_t base = smb + (t % 3) * STGB;
            int k0 = t * BK;
#pragma unroll
            for (int p = 0; p < 4; p++) cp16(base + adst[p], asrc[p] + k0, asz[p]);
#pragma unroll
            for (int p = 0; p < 4; p++)
                cp16(base + bdst[p], bsrc[p] + (size_t)k0 * HID, 16);
        }
        CP_COMMIT();
    }

#pragma unroll
    for (int mt = 0; mt < 2; mt++) {
        int r = mbase + wm * 32 + mt * 16 + gid;
#pragma unroll
        for (int nt = 0; nt < 8; nt++) {
            int c = ncol + wn * 64 + nt * 8 + 2 * tig;
            *(float2*)&C[(size_t)r * HID + c] =
                make_float2(acc[mt][nt][0], acc[mt][nt][1]);
            *(float2*)&C[(size_t)(r + 8) * HID + c] =
                make_float2(acc[mt][nt][2], acc[mt][nt][3]);
        }
    }
}

// ---------------- GEMM2: [Mpad,4096] x [4096,1024], atomic epilogue -------------
__global__ __launch_bounds__(256) void k_gemm2_mma(const float* __restrict__ w_down,
                                                   float* __restrict__ out) {
    extern __shared__ float sm[];
    int total = g_offpad[NEXP];
    int mbase = blockIdx.y * BM;
    if (mbase >= total) return;
    int e = 0;
#pragma unroll
    for (int i = 0; i < NEXP; i++) if (mbase >= g_offpad[i + 1]) e = i + 1;

    const float* W = w_down + (size_t)e * HID * DIM;
    int ncol = blockIdx.x * BN;

    int tid = threadIdx.x;
    uint32_t smb = smem_u32(sm);

    int arow0 = tid >> 3, akf = (tid & 7) * 4;
    uint32_t adst[4]; const float* asrc[4];
#pragma unroll
    for (int p = 0; p < 4; p++) {
        int row = arow0 + p * 32;
        adst[p] = (uint32_t)(row * SA + akf) * 4;
        asrc[p] = g_hg + (size_t)(mbase + row) * HID + akf;
    }
    int bkr0 = tid >> 5, bnf = (tid & 31) * 4;
    uint32_t bdst[4]; const float* bsrc[4];
#pragma unroll
    for (int p = 0; p < 4; p++) {
        int kr = bkr0 + p * 8;
        bdst[p] = (uint32_t)(ASTG + kr * SB + bnf) * 4;
        bsrc[p] = W + (size_t)kr * DIM + ncol + bnf;
    }

    int lane = tid & 31, gid = lane >> 2, tig = lane & 3;
    int wm = (tid >> 5) & 3, wn = tid >> 7;
    int r0 = wm * 32 + gid, cb = wn * 64 + gid;

    float acc[2][8][4];
#pragma unroll
    for (int mt = 0; mt < 2; mt++)
#pragma unroll
        for (int nt = 0; nt < 8; nt++)
#pragma unroll
            for (int q = 0; q < 4; q++) acc[mt][nt][q] = 0.f;

    const int NT = HID / BK;            // 128
#pragma unroll
    for (int t = 0; t < 3; t++) {
        uint32_t base = smb + t * STGB;
        int k0 = t * BK;
#pragma unroll
        for (int p = 0; p < 4; p++) cp16(base + adst[p], asrc[p] + k0, 16);
#pragma unroll
        for (int p = 0; p < 4; p++)
            cp16(base + bdst[p], bsrc[p] + (size_t)k0 * DIM, 16);
        CP_COMMIT();
    }

    for (int i = 0; i < NT; i++) {
        CP_WAIT2();
        __syncthreads();
        const uint32_t* Au = (const uint32_t*)(sm + (i % 3) * STGF);
        const uint32_t* Bu = Au + ASTG;
#pragma unroll
        for (int ks = 0; ks < 4; ks++) {
            int k = ks * 8;
            uint32_t a[2][4], b[8][2];
#pragma unroll
            for (int mt = 0; mt < 2; mt++) {
                int rr = r0 + mt * 16;
                a[mt][0] = Au[rr * SA + k + tig];
                a[mt][1] = Au[(rr + 8) * SA + k + tig];
                a[mt][2] = Au[rr * SA + k + 4 + tig];
                a[mt][3] = Au[(rr + 8) * SA + k + 4 + tig];
            }
#pragma unroll
            for (int nt = 0; nt < 8; nt++) {
                int cc = cb + nt * 8;
                b[nt][0] = rna13(Bu[(k + tig) * SB + cc]);
                b[nt][1] = rna13(Bu[(k + tig + 4) * SB + cc]);
            }
#pragma unroll
            for (int mt = 0; mt < 2; mt++)
#pragma unroll
                for (int nt = 0; nt < 8; nt++)
                    mma_tf32(acc[mt][nt], a[mt], b[nt]);
        }
        __syncthreads();
        int t = i + 3;
        if (t < NT) {
            uint32_t base = smb + (t % 3) * STGB;
            int k0 = t * BK;
#pragma unroll
            for (int p = 0; p < 4; p++) cp16(base + adst[p], asrc[p] + k0, 16);
#pragma unroll
            for (int p = 0; p < 4; p++)
                cp16(base + bdst[p], bsrc[p] + (size_t)k0 * DIM, 16);
        }
        CP_COMMIT();
    }

#pragma unroll
    for (int mt = 0; mt < 2; mt++) {
        int slot = mbase + wm * 32 + mt * 16 + gid;
        int tok0 = g_perm[slot],     tok1 = g_perm[slot + 8];
        float w0 = g_permw[slot],    w1 = g_permw[slot + 8];
#pragma unroll
        for (int nt = 0; nt < 8; nt++) {
            int c = ncol + wn * 64 + nt * 8 + 2 * tig;
            if (tok0 >= 0) {
                float* op = out + (size_t)tok0 * DIM + c;
                atomicAdd(op,     w0 * acc[mt][nt][0]);
                atomicAdd(op + 1, w0 * acc[mt][nt][1]);
            }
            if (tok1 >= 0) {
                float* op = out + (size_t)tok1 * DIM + c;
                atomicAdd(op,     w1 * acc[mt][nt][2]);
                atomicAdd(op + 1, w1 * acc[mt][nt][3]);
            }
        }
    }
}

// ---------------- launch ----------------
extern "C" void kernel_launch(void* const* d_in, const int* in_sizes, int n_in,
                              void* d_out, int out_size) {
    const float* x      = (const float*)d_in[0];
    const float* gate_w = (const float*)d_in[1];
    const float* w_gate = (const float*)d_in[2];
    const float* w_up   = (const float*)d_in[3];
    const float* w_down = (const float*)d_in[4];
    float* out = (float*)d_out;

    cudaFuncSetAttribute(k_gemm1_mma, cudaFuncAttributeMaxDynamicSharedMemorySize,
                         SMEM_DYN);
    cudaFuncSetAttribute(k_gemm2_mma, cudaFuncAttributeMaxDynamicSharedMemorySize,
                         SMEM_DYN);

    k_init<<<MAXPAD / 256, 256>>>();
    k_zero_out<<<2048, 256>>>((float4*)out, (T_TOK * DIM) / 4);
    k_gate<<<T_TOK / 8, 256>>>(x, gate_w);
    k_offsets<<<1, 32>>>(out);
    k_scatter<<<(2 * T_TOK) / 256, 256>>>();

    k_gemm1_mma<<<dim3(2 * HID / BN, NMPAD), 256, SMEM_DYN>>>(x, w_gate, w_up);
    k_silu<<<1184, 256>>>();
    k_gemm2_mma<<<dim3(DIM / BN, NMPAD), 256, SMEM_DYN>>>(w_down, out);
}

// round 7
// speedup vs baseline: 1.0679x; 1.0222x over previous
#include <cuda_runtime.h>
#include <cstdint>

#define T_TOK 8192
#define DIM   1024
#define HID   4096
#define NEXP  8
#define BM 128
#define BN 128
#define BK 32
#define NMPAD  136
#define MAXPAD (NMPAD * BM)

#define SA 36                       // A smem row stride (floats)
#define SB 136                      // B smem row stride (floats)
#define ASTG (BM * SA)              // 4608 floats
#define BSTG (BK * SB)              // 4352 floats
#define STGF (ASTG + BSTG)          // 8960 floats per stage
#define STGB (STGF * 4)             // 35840 bytes
#define SMEM_DYN (3 * STGB)         // 107520 bytes -> 2 CTAs/SM

// ---------------- scratch ----------------
__device__ float g_hg[(size_t)MAXPAD * HID];   // h = silu(g)*u (pre-rounded)
__device__ float g_hu[(size_t)MAXPAD * HID];   // raw gate accumulators g
__device__ int   g_perm[MAXPAD];
__device__ float g_permw[MAXPAD];
__device__ int   g_offpad[NEXP + 1];
__device__ int   g_cnt[NEXP];
__device__ int   g_cursor[NEXP];
__device__ float g_probsum[NEXP];
__device__ int   g_topi[T_TOK * 2];
__device__ float g_topw[T_TOK * 2];

// ---------------- helpers ----------------
__device__ __forceinline__ uint32_t smem_u32(const void* p) {
    uint32_t a;
    asm("{ .reg .u64 t; cvta.to.shared.u64 t, %1; cvt.u32.u64 %0, t; }"
        : "=r"(a) : "l"(p));
    return a;
}
__device__ __forceinline__ float frna(float x) {
    uint32_t o; asm("cvt.rna.tf32.f32 %0, %1;" : "=r"(o) : "f"(x));
    return __uint_as_float(o);
}
// RNA-to-tf32 via integer add (HMMA truncates to top 19 bits): bit-identical
// to cvt.rna.tf32 at full ALU rate.
__device__ __forceinline__ uint32_t rna13(uint32_t x) { return x + 0x1000u; }

__device__ __forceinline__ void cp16(uint32_t d, const float* s, uint32_t sz) {
    asm volatile("cp.async.cg.shared.global [%0], [%1], 16, %2;"
                 :: "r"(d), "l"(s), "r"(sz));
}
#define CP_COMMIT() asm volatile("cp.async.commit_group;" ::: "memory")
#define CP_WAIT1()  asm volatile("cp.async.wait_group 1;" ::: "memory")

__device__ __forceinline__ void mma_tf32(float* c, const uint32_t* a,
                                         const uint32_t* b) {
    asm volatile(
        "mma.sync.aligned.m16n8k8.row.col.f32.tf32.tf32.f32 "
        "{%0,%1,%2,%3}, {%4,%5,%6,%7}, {%8,%9}, {%0,%1,%2,%3};"
        : "+f"(c[0]), "+f"(c[1]), "+f"(c[2]), "+f"(c[3])
        : "r"(a[0]), "r"(a[1]), "r"(a[2]), "r"(a[3]), "r"(b[0]), "r"(b[1]));
}

// ---------------- small kernels ----------------
__global__ void k_init() {
    int i = blockIdx.x * blockDim.x + threadIdx.x;
    if (i < NEXP) { g_cnt[i] = 0; g_cursor[i] = 0; g_probsum[i] = 0.f; }
    if (i < MAXPAD) g_perm[i] = -1;
}

__global__ void k_zero_out(float4* out, int n4) {
    float4 z = make_float4(0.f, 0.f, 0.f, 0.f);
    for (int i = blockIdx.x * blockDim.x + threadIdx.x; i < n4;
         i += gridDim.x * blockDim.x)
        out[i] = z;
}

__global__ void k_gate(const float* __restrict__ x, const float* __restrict__ gw) {
    int gwarp = (blockIdx.x * blockDim.x + threadIdx.x) >> 5;
    int lane  = threadIdx.x & 31;
    if (gwarp >= T_TOK) return;
    const float* xr = x + (size_t)gwarp * DIM;

    float acc[NEXP];
#pragma unroll
    for (int e = 0; e < NEXP; e++) acc[e] = 0.f;
    for (int i = lane; i < DIM; i += 32) {
        float xv = xr[i];
        float4 g0 = *(const float4*)(gw + (size_t)i * NEXP);
        float4 g1 = *(const float4*)(gw + (size_t)i * NEXP + 4);
        acc[0] += xv * g0.x; acc[1] += xv * g0.y;
        acc[2] += xv * g0.z; acc[3] += xv * g0.w;
        acc[4] += xv * g1.x; acc[5] += xv * g1.y;
        acc[6] += xv * g1.z; acc[7] += xv * g1.w;
    }
#pragma unroll
    for (int off = 16; off > 0; off >>= 1)
#pragma unroll
        for (int e = 0; e < NEXP; e++)
            acc[e] += __shfl_xor_sync(0xffffffffu, acc[e], off);

    float mx = acc[0];
#pragma unroll
    for (int e = 1; e < NEXP; e++) mx = fmaxf(mx, acc[e]);
    float p[NEXP], s = 0.f;
#pragma unroll
    for (int e = 0; e < NEXP; e++) { p[e] = __expf(acc[e] - mx); s += p[e]; }
    float inv = 1.f / s;
    if (lane < NEXP) atomicAdd(&g_probsum[lane], p[lane] * inv);

    if (lane == 0) {
        int i0 = 0;
#pragma unroll
        for (int e = 1; e < NEXP; e++) if (acc[e] > acc[i0]) i0 = e;
        int i1 = (i0 == 0) ? 1 : 0;
#pragma unroll
        for (int e = 0; e < NEXP; e++)
            if (e != i0 && acc[e] > acc[i1]) i1 = e;
        float m2 = fmaxf(acc[i0], acc[i1]);
        float e0 = __expf(acc[i0] - m2), e1 = __expf(acc[i1] - m2);
        float inv2 = 1.f / (e0 + e1);
        g_topi[2 * gwarp]     = i0; g_topw[2 * gwarp]     = e0 * inv2;
        g_topi[2 * gwarp + 1] = i1; g_topw[2 * gwarp + 1] = e1 * inv2;
        atomicAdd(&g_cnt[i0], 1);
        atomicAdd(&g_cnt[i1], 1);
    }
}

__global__ void k_offsets(float* __restrict__ out) {
    if (threadIdx.x != 0 || blockIdx.x != 0) return;
    int off = 0;
    for (int e = 0; e < NEXP; e++) {
        g_offpad[e] = off;
        off += ((g_cnt[e] + BM - 1) / BM) * BM;
    }
    g_offpad[NEXP] = off;
    float loss = 0.f;
    const float invT = 1.f / (float)T_TOK;
    for (int e = 0; e < NEXP; e++) {
        float m = g_probsum[e] * invT;
        out[(size_t)T_TOK * DIM + 1 + e] = m;
        loss += m * m;
    }
    out[(size_t)T_TOK * DIM] = (float)NEXP * loss;
}

__global__ void k_scatter() {
    int t = blockIdx.x * blockDim.x + threadIdx.x;
    if (t >= 2 * T_TOK) return;
    int e = g_topi[t];
    int pos = g_offpad[e] + atomicAdd(&g_cursor[e], 1);
    g_perm[pos]  = t >> 1;
    g_permw[pos] = g_topw[t];
}

// ---------------- GEMM1 core (gate or up), 128x128x32, x gathered --------------
// UP=0: C_raw = A@Wg -> g_hu.   UP=1: u = A@Wu; h = frna(silu(g)*u) -> g_hg.
template<int UP>
__device__ __forceinline__ void gemm1_body(const float* __restrict__ x,
                                           const float* __restrict__ w) {
    extern __shared__ float sm[];
    int total = g_offpad[NEXP];
    int mbase = blockIdx.y * BM;
    if (mbase >= total) return;
    int e = 0;
#pragma unroll
    for (int i = 0; i < NEXP; i++) if (mbase >= g_offpad[i + 1]) e = i + 1;

    const float* W = w + (size_t)e * DIM * HID;
    int ncol = blockIdx.x * BN;

    int tid = threadIdx.x;
    uint32_t smb = smem_u32(sm);

    int arow0 = tid >> 3, akf = (tid & 7) * 4;
    uint32_t adst[4]; const float* asrc[4]; uint32_t asz[4];
#pragma unroll
    for (int p = 0; p < 4; p++) {
        int row = arow0 + p * 32;
        adst[p] = (uint32_t)(row * SA + akf) * 4;
        int tok = g_perm[mbase + row];
        asrc[p] = x + ((tok >= 0) ? (size_t)tok * DIM : 0) + akf;
        asz[p]  = (tok >= 0) ? 16u : 0u;
    }
    int bkr0 = tid >> 5, bnf = (tid & 31) * 4;
    uint32_t bdst[4]; const float* bsrc[4];
#pragma unroll
    for (int p = 0; p < 4; p++) {
        int kr = bkr0 + p * 8;
        bdst[p] = (uint32_t)(ASTG + kr * SB + bnf) * 4;
        bsrc[p] = W + (size_t)kr * HID + ncol + bnf;
    }

    int lane = tid & 31, gid = lane >> 2, tig = lane & 3;
    int wm = (tid >> 5) & 3, wn = tid >> 7;
    int r0 = wm * 32 + gid, cb = wn * 64 + gid;

    float acc[2][8][4];
#pragma unroll
    for (int mt = 0; mt < 2; mt++)
#pragma unroll
        for (int nt = 0; nt < 8; nt++)
#pragma unroll
            for (int q = 0; q < 4; q++) acc[mt][nt][q] = 0.f;

    const int NT = DIM / BK;             // 32
#pragma unroll
    for (int t = 0; t < 2; t++) {        // prologue: 2 stages
        uint32_t base = smb + t * STGB;
        int k0 = t * BK;
#pragma unroll
        for (int p = 0; p < 4; p++) cp16(base + adst[p], asrc[p] + k0, asz[p]);
#pragma unroll
        for (int p = 0; p < 4; p++)
            cp16(base + bdst[p], bsrc[p] + (size_t)k0 * HID, 16);
        CP_COMMIT();
    }

    for (int i = 0; i < NT; i++) {
        CP_WAIT1();
        __syncthreads();
        int t = i + 2;
        if (t < NT) {
            uint32_t base = smb + (t % 3) * STGB;
            int k0 = t * BK;
#pragma unroll
            for (int p = 0; p < 4; p++) cp16(base + adst[p], asrc[p] + k0, asz[p]);
#pragma unroll
            for (int p = 0; p < 4; p++)
                cp16(base + bdst[p], bsrc[p] + (size_t)k0 * HID, 16);
        }
        CP_COMMIT();

        const uint32_t* Au = (const uint32_t*)(sm + (i % 3) * STGF);
        const uint32_t* Bu = Au + ASTG;
#pragma unroll
        for (int ks = 0; ks < 4; ks++) {
            int k = ks * 8;
            uint32_t a[2][4], b[8][2];
#pragma unroll
            for (int mt = 0; mt < 2; mt++) {
                int rr = r0 + mt * 16;
                a[mt][0] = rna13(Au[rr * SA + k + tig]);
                a[mt][1] = rna13(Au[(rr + 8) * SA + k + tig]);
                a[mt][2] = rna13(Au[rr * SA + k + 4 + tig]);
                a[mt][3] = rna13(Au[(rr + 8) * SA + k + 4 + tig]);
            }
#pragma unroll
            for (int nt = 0; nt < 8; nt++) {
                int cc = cb + nt * 8;
                b[nt][0] = rna13(Bu[(k + tig) * SB + cc]);
                b[nt][1] = rna13(Bu[(k + tig + 4) * SB + cc]);
            }
#pragma unroll
            for (int mt = 0; mt < 2; mt++)
#pragma unroll
                for (int nt = 0; nt < 8; nt++)
                    mma_tf32(acc[mt][nt], a[mt], b[nt]);
        }
    }

#pragma unroll
    for (int mt = 0; mt < 2; mt++) {
        int r = mbase + wm * 32 + mt * 16 + gid;
#pragma unroll
        for (int nt = 0; nt < 8; nt++) {
            int c = ncol + wn * 64 + nt * 8 + 2 * tig;
            if (UP) {
                // fused silu: read raw g, combine with u, write h
                float2 ga = *(float2*)&g_hu[(size_t)r * HID + c];
                float2 gb = *(float2*)&g_hu[(size_t)(r + 8) * HID + c];
                float h0 = frna(ga.x * (1.f / (1.f + __expf(-ga.x))) * acc[mt][nt][0]);
                float h1 = frna(ga.y * (1.f / (1.f + __expf(-ga.y))) * acc[mt][nt][1]);
                float h2 = frna(gb.x * (1.f / (1.f + __expf(-gb.x))) * acc[mt][nt][2]);
                float h3 = frna(gb.y * (1.f / (1.f + __expf(-gb.y))) * acc[mt][nt][3]);
                *(float2*)&g_hg[(size_t)r * HID + c]       = make_float2(h0, h1);
                *(float2*)&g_hg[(size_t)(r + 8) * HID + c] = make_float2(h2, h3);
            } else {
                *(float2*)&g_hu[(size_t)r * HID + c] =
                    make_float2(acc[mt][nt][0], acc[mt][nt][1]);
                *(float2*)&g_hu[(size_t)(r + 8) * HID + c] =
                    make_float2(acc[mt][nt][2], acc[mt][nt][3]);
            }
        }
    }
}

__global__ __launch_bounds__(256) void k_g1gate(const float* __restrict__ x,
                                                const float* __restrict__ wg) {
    gemm1_body<0>(x, wg);
}
__global__ __launch_bounds__(256) void k_g1up(const float* __restrict__ x,
                                              const float* __restrict__ wu) {
    gemm1_body<1>(x, wu);
}

// ---------------- GEMM2: [Mpad,4096] x [4096,1024], atomic epilogue -------------
__global__ __launch_bounds__(256) void k_gemm2_mma(const float* __restrict__ w_down,
                                                   float* __restrict__ out) {
    extern __shared__ float sm[];
    int total = g_offpad[NEXP];
    int mbase = blockIdx.y * BM;
    if (mbase >= total) return;
    int e = 0;
#pragma unroll
    for (int i = 0; i < NEXP; i++) if (mbase >= g_offpad[i + 1]) e = i + 1;

    const float* W = w_down + (size_t)e * HID * DIM;
    int ncol = blockIdx.x * BN;

    int tid = threadIdx.x;
    uint32_t smb = smem_u32(sm);

    int arow0 = tid >> 3, akf = (tid & 7) * 4;
    uint32_t adst[4]; const float* asrc[4];
#pragma unroll
    for (int p = 0; p < 4; p++) {
        int row = arow0 + p * 32;
        adst[p] = (uint32_t)(row * SA + akf) * 4;
        asrc[p] = g_hg + (size_t)(mbase + row) * HID + akf;
    }
    int bkr0 = tid >> 5, bnf = (tid & 31) * 4;
    uint32_t bdst[4]; const float* bsrc[4];
#pragma unroll
    for (int p = 0; p < 4; p++) {
        int kr = bkr0 + p * 8;
        bdst[p] = (uint32_t)(ASTG + kr * SB + bnf) * 4;
        bsrc[p] = W + (size_t)kr * DIM + ncol + bnf;
    }

    int lane = tid & 31, gid = lane >> 2, tig = lane & 3;
    int wm = (tid >> 5) & 3, wn = tid >> 7;
    int r0 = wm * 32 + gid, cb = wn * 64 + gid;

    float acc[2][8][4];
#pragma unroll
    for (int mt = 0; mt < 2; mt++)
#pragma unroll
        for (int nt = 0; nt < 8; nt++)
#pragma unroll
            for (int q = 0; q < 4; q++) acc[mt][nt][q] = 0.f;

    const int NT = HID / BK;            // 128
#pragma unroll
    for (int t = 0; t < 2; t++) {
        uint32_t base = smb + t * STGB;
        int k0 = t * BK;
#pragma unroll
        for (int p = 0; p < 4; p++) cp16(base + adst[p], asrc[p] + k0, 16);
#pragma unroll
        for (int p = 0; p < 4; p++)
            cp16(base + bdst[p], bsrc[p] + (size_t)k0 * DIM, 16);
        CP_COMMIT();
    }

    for (int i = 0; i < NT; i++) {
        CP_WAIT1();
        __syncthreads();
        int t = i + 2;
        if (t < NT) {
            uint32_t base = smb + (t % 3) * STGB;
            int k0 = t * BK;
#pragma unroll
            for (int p = 0; p < 4; p++) cp16(base + adst[p], asrc[p] + k0, 16);
#pragma unroll
            for (int p = 0; p < 4; p++)
                cp16(base + bdst[p], bsrc[p] + (size_t)k0 * DIM, 16);
        }
        CP_COMMIT();

        const uint32_t* Au = (const uint32_t*)(sm + (i % 3) * STGF);
        const uint32_t* Bu = Au + ASTG;
#pragma unroll
        for (int ks = 0; ks < 4; ks++) {
            int k = ks * 8;
            uint32_t a[2][4], b[8][2];
#pragma unroll
            for (int mt = 0; mt < 2; mt++) {
                int rr = r0 + mt * 16;
                a[mt][0] = Au[rr * SA + k + tig];
                a[mt][1] = Au[(rr + 8) * SA + k + tig];
                a[mt][2] = Au[rr * SA + k + 4 + tig];
                a[mt][3] = Au[(rr + 8) * SA + k + 4 + tig];
            }
#pragma unroll
            for (int nt = 0; nt < 8; nt++) {
                int cc = cb + nt * 8;
                b[nt][0] = rna13(Bu[(k + tig) * SB + cc]);
                b[nt][1] = rna13(Bu[(k + tig + 4) * SB + cc]);
            }
#pragma unroll
            for (int mt = 0; mt < 2; mt++)
#pragma unroll
                for (int nt = 0; nt < 8; nt++)
                    mma_tf32(acc[mt][nt], a[mt], b[nt]);
        }
    }

#pragma unroll
    for (int mt = 0; mt < 2; mt++) {
        int slot = mbase + wm * 32 + mt * 16 + gid;
        int tok0 = g_perm[slot],     tok1 = g_perm[slot + 8];
        float w0 = g_permw[slot],    w1 = g_permw[slot + 8];
#pragma unroll
        for (int nt = 0; nt < 8; nt++) {
            int c = ncol + wn * 64 + nt * 8 + 2 * tig;
            if (tok0 >= 0) {
                float* op = out + (size_t)tok0 * DIM + c;
                atomicAdd(op,     w0 * acc[mt][nt][0]);
                atomicAdd(op + 1, w0 * acc[mt][nt][1]);
            }
            if (tok1 >= 0) {
                float* op = out + (size_t)tok1 * DIM + c;
                atomicAdd(op,     w1 * acc[mt][nt][2]);
                atomicAdd(op + 1, w1 * acc[mt][nt][3]);
            }
        }
    }
}

// ---------------- launch ----------------
extern "C" void kernel_launch(void* const* d_in, const int* in_sizes, int n_in,
                              void* d_out, int out_size) {
    const float* x      = (const float*)d_in[0];
    const float* gate_w = (const float*)d_in[1];
    const float* w_gate = (const float*)d_in[2];
    const float* w_up   = (const float*)d_in[3];
    const float* w_down = (const float*)d_in[4];
    float* out = (float*)d_out;

    cudaFuncSetAttribute(k_g1gate, cudaFuncAttributeMaxDynamicSharedMemorySize,
                         SMEM_DYN);
    cudaFuncSetAttribute(k_g1up, cudaFuncAttributeMaxDynamicSharedMemorySize,
                         SMEM_DYN);
    cudaFuncSetAttribute(k_gemm2_mma, cudaFuncAttributeMaxDynamicSharedMemorySize,
                         SMEM_DYN);

    k_init<<<MAXPAD / 256, 256>>>();
    k_zero_out<<<2048, 256>>>((float4*)out, (T_TOK * DIM) / 4);
    k_gate<<<T_TOK / 8, 256>>>(x, gate_w);
    k_offsets<<<1, 32>>>(out);
    k_scatter<<<(2 * T_TOK) / 256, 256>>>();

    k_g1gate<<<dim3(HID / BN, NMPAD), 256, SMEM_DYN>>>(x, w_gate);
    k_g1up<<<dim3(HID / BN, NMPAD), 256, SMEM_DYN>>>(x, w_up);
    k_gemm2_mma<<<dim3(DIM / BN, NMPAD), 256, SMEM_DYN>>>(w_down, out);
}

// round 8
// speedup vs baseline: 1.0835x; 1.0146x over previous
#include <cuda_runtime.h>
#include <cstdint>

#define T_TOK 8192
#define DIM   1024
#define HID   4096
#define NEXP  8
#define BM 128
#define BN 128
#define BK 32
#define NMPAD  136
#define MAXPAD (NMPAD * BM)

#define SA 36                       // A smem row stride (floats)
#define SB 136                      // B smem row stride (floats)
#define ASTG (BM * SA)              // 4608 floats
#define BSTG (BK * SB)              // 4352 floats
#define STGF (ASTG + BSTG)          // 8960 floats per stage
#define STGB (STGF * 4)             // 35840 bytes
#define SMEM_DYN (3 * STGB)         // 107520 bytes -> 2 CTAs/SM

// ---------------- scratch ----------------
__device__ float g_hg[(size_t)MAXPAD * HID];   // h = silu(g)*u (pre-rounded)
__device__ float g_hu[(size_t)MAXPAD * HID];   // raw gate accumulators g
__device__ int   g_perm[MAXPAD];
__device__ float g_permw[MAXPAD];
__device__ int   g_offpad[NEXP + 1];
__device__ int   g_cnt[NEXP];
__device__ int   g_cursor[NEXP];
__device__ float g_probsum[NEXP];
__device__ int   g_topi[T_TOK * 2];
__device__ float g_topw[T_TOK * 2];

// ---------------- helpers ----------------
__device__ __forceinline__ uint32_t smem_u32(const void* p) {
    uint32_t a;
    asm("{ .reg .u64 t; cvta.to.shared.u64 t, %1; cvt.u32.u64 %0, t; }"
        : "=r"(a) : "l"(p));
    return a;
}
__device__ __forceinline__ float frna(float x) {
    uint32_t o; asm("cvt.rna.tf32.f32 %0, %1;" : "=r"(o) : "f"(x));
    return __uint_as_float(o);
}
// RNA-to-tf32 via integer add (HMMA truncates to top 19 bits): bit-identical
// to cvt.rna.tf32 at full ALU rate.
__device__ __forceinline__ uint32_t rna13(uint32_t x) { return x + 0x1000u; }

__device__ __forceinline__ void cp16(uint32_t d, const float* s, uint32_t sz) {
    asm volatile("cp.async.cg.shared.global [%0], [%1], 16, %2;"
                 :: "r"(d), "l"(s), "r"(sz));
}
#define CP_COMMIT() asm volatile("cp.async.commit_group;" ::: "memory")
#define CP_WAIT1()  asm volatile("cp.async.wait_group 1;" ::: "memory")

__device__ __forceinline__ void mma_tf32(float* c, const uint32_t* a,
                                         const uint32_t* b) {
    asm volatile(
        "mma.sync.aligned.m16n8k8.row.col.f32.tf32.tf32.f32 "
        "{%0,%1,%2,%3}, {%4,%5,%6,%7}, {%8,%9}, {%0,%1,%2,%3};"
        : "+f"(c[0]), "+f"(c[1]), "+f"(c[2]), "+f"(c[3])
        : "r"(a[0]), "r"(a[1]), "r"(a[2]), "r"(a[3]), "r"(b[0]), "r"(b[1]));
}

// 16x8 tf32 A-fragment as four 8x8 b16 matrices: one ldmatrix.x4.
// Lane-group addressing (set up by caller) makes r0..r3 = a0..a3 exactly.
__device__ __forceinline__ void ldsm_x4(uint32_t* r, uint32_t addr) {
    asm volatile("ldmatrix.sync.aligned.m8n8.x4.shared.b16 {%0,%1,%2,%3}, [%4];"
                 : "=r"(r[0]), "=r"(r[1]), "=r"(r[2]), "=r"(r[3]) : "r"(addr));
}

// ---------------- small kernels ----------------
__global__ void k_init() {
    int i = blockIdx.x * blockDim.x + threadIdx.x;
    if (i < NEXP) { g_cnt[i] = 0; g_cursor[i] = 0; g_probsum[i] = 0.f; }
    if (i < MAXPAD) g_perm[i] = -1;
}

__global__ void k_zero_out(float4* out, int n4) {
    float4 z = make_float4(0.f, 0.f, 0.f, 0.f);
    for (int i = blockIdx.x * blockDim.x + threadIdx.x; i < n4;
         i += gridDim.x * blockDim.x)
        out[i] = z;
}

__global__ void k_gate(const float* __restrict__ x, const float* __restrict__ gw) {
    int gwarp = (blockIdx.x * blockDim.x + threadIdx.x) >> 5;
    int lane  = threadIdx.x & 31;
    if (gwarp >= T_TOK) return;
    const float* xr = x + (size_t)gwarp * DIM;

    float acc[NEXP];
#pragma unroll
    for (int e = 0; e < NEXP; e++) acc[e] = 0.f;
    for (int i = lane; i < DIM; i += 32) {
        float xv = xr[i];
        float4 g0 = *(const float4*)(gw + (size_t)i * NEXP);
        float4 g1 = *(const float4*)(gw + (size_t)i * NEXP + 4);
        acc[0] += xv * g0.x; acc[1] += xv * g0.y;
        acc[2] += xv * g0.z; acc[3] += xv * g0.w;
        acc[4] += xv * g1.x; acc[5] += xv * g1.y;
        acc[6] += xv * g1.z; acc[7] += xv * g1.w;
    }
#pragma unroll
    for (int off = 16; off > 0; off >>= 1)
#pragma unroll
        for (int e = 0; e < NEXP; e++)
            acc[e] += __shfl_xor_sync(0xffffffffu, acc[e], off);

    float mx = acc[0];
#pragma unroll
    for (int e = 1; e < NEXP; e++) mx = fmaxf(mx, acc[e]);
    float p[NEXP], s = 0.f;
#pragma unroll
    for (int e = 0; e < NEXP; e++) { p[e] = __expf(acc[e] - mx); s += p[e]; }
    float inv = 1.f / s;
    if (lane < NEXP) atomicAdd(&g_probsum[lane], p[lane] * inv);

    if (lane == 0) {
        int i0 = 0;
#pragma unroll
        for (int e = 1; e < NEXP; e++) if (acc[e] > acc[i0]) i0 = e;
        int i1 = (i0 == 0) ? 1 : 0;
#pragma unroll
        for (int e = 0; e < NEXP; e++)
            if (e != i0 && acc[e] > acc[i1]) i1 = e;
        float m2 = fmaxf(acc[i0], acc[i1]);
        float e0 = __expf(acc[i0] - m2), e1 = __expf(acc[i1] - m2);
        float inv2 = 1.f / (e0 + e1);
        g_topi[2 * gwarp]     = i0; g_topw[2 * gwarp]     = e0 * inv2;
        g_topi[2 * gwarp + 1] = i1; g_topw[2 * gwarp + 1] = e1 * inv2;
        atomicAdd(&g_cnt[i0], 1);
        atomicAdd(&g_cnt[i1], 1);
    }
}

__global__ void k_offsets(float* __restrict__ out) {
    if (threadIdx.x != 0 || blockIdx.x != 0) return;
    int off = 0;
    for (int e = 0; e < NEXP; e++) {
        g_offpad[e] = off;
        off += ((g_cnt[e] + BM - 1) / BM) * BM;
    }
    g_offpad[NEXP] = off;
    float loss = 0.f;
    const float invT = 1.f / (float)T_TOK;
    for (int e = 0; e < NEXP; e++) {
        float m = g_probsum[e] * invT;
        out[(size_t)T_TOK * DIM + 1 + e] = m;
        loss += m * m;
    }
    out[(size_t)T_TOK * DIM] = (float)NEXP * loss;
}

__global__ void k_scatter() {
    int t = blockIdx.x * blockDim.x + threadIdx.x;
    if (t >= 2 * T_TOK) return;
    int e = g_topi[t];
    int pos = g_offpad[e] + atomicAdd(&g_cursor[e], 1);
    g_perm[pos]  = t >> 1;
    g_permw[pos] = g_topw[t];
}

// ---------------- GEMM1 core (gate or up), 128x128x32, x gathered --------------
// UP=0: C_raw = A@Wg -> g_hu.   UP=1: u = A@Wu; h = frna(silu(g)*u) -> g_hg.
template<int UP>
__device__ __forceinline__ void gemm1_body(const float* __restrict__ x,
                                           const float* __restrict__ w) {
    extern __shared__ float sm[];
    int total = g_offpad[NEXP];
    int mbase = blockIdx.y * BM;
    if (mbase >= total) return;
    int e = 0;
#pragma unroll
    for (int i = 0; i < NEXP; i++) if (mbase >= g_offpad[i + 1]) e = i + 1;

    const float* W = w + (size_t)e * DIM * HID;
    int ncol = blockIdx.x * BN;

    int tid = threadIdx.x;
    uint32_t smb = smem_u32(sm);

    int arow0 = tid >> 3, akf = (tid & 7) * 4;
    uint32_t adst[4]; const float* asrc[4]; uint32_t asz[4];
#pragma unroll
    for (int p = 0; p < 4; p++) {
        int row = arow0 + p * 32;
        adst[p] = (uint32_t)(row * SA + akf) * 4;
        int tok = g_perm[mbase + row];
        asrc[p] = x + ((tok >= 0) ? (size_t)tok * DIM : 0) + akf;
        asz[p]  = (tok >= 0) ? 16u : 0u;
    }
    int bkr0 = tid >> 5, bnf = (tid & 31) * 4;
    uint32_t bdst[4]; const float* bsrc[4];
#pragma unroll
    for (int p = 0; p < 4; p++) {
        int kr = bkr0 + p * 8;
        bdst[p] = (uint32_t)(ASTG + kr * SB + bnf) * 4;
        bsrc[p] = W + (size_t)kr * HID + ncol + bnf;
    }

    int lane = tid & 31, gid = lane >> 2, tig = lane & 3;
    int wm = (tid >> 5) & 3, wn = tid >> 7;
    int cb = wn * 64 + gid;
    // ldmatrix lane address: rows (lane&15), col-halves via (lane>>4)*4
    uint32_t aln = (uint32_t)(((wm * 32 + (lane & 15)) * SA + (lane >> 4) * 4) * 4);

    float acc[2][8][4];
#pragma unroll
    for (int mt = 0; mt < 2; mt++)
#pragma unroll
        for (int nt = 0; nt < 8; nt++)
#pragma unroll
            for (int q = 0; q < 4; q++) acc[mt][nt][q] = 0.f;

    const int NT = DIM / BK;             // 32
#pragma unroll
    for (int t = 0; t < 2; t++) {        // prologue: 2 stages
        uint32_t base = smb + t * STGB;
        int k0 = t * BK;
#pragma unroll
        for (int p = 0; p < 4; p++) cp16(base + adst[p], asrc[p] + k0, asz[p]);
#pragma unroll
        for (int p = 0; p < 4; p++)
            cp16(base + bdst[p], bsrc[p] + (size_t)k0 * HID, 16);
        CP_COMMIT();
    }

    for (int i = 0; i < NT; i++) {
        CP_WAIT1();
        __syncthreads();
        int t = i + 2;
        if (t < NT) {
            uint32_t base = smb + (t % 3) * STGB;
            int k0 = t * BK;
#pragma unroll
            for (int p = 0; p < 4; p++) cp16(base + adst[p], asrc[p] + k0, asz[p]);
#pragma unroll
            for (int p = 0; p < 4; p++)
                cp16(base + bdst[p], bsrc[p] + (size_t)k0 * HID, 16);
        }
        CP_COMMIT();

        uint32_t abase = smb + (uint32_t)(i % 3) * STGB + aln;
        const uint32_t* Bu = (const uint32_t*)(sm + (i % 3) * STGF) + ASTG;
#pragma unroll
        for (int ks = 0; ks < 4; ks++) {
            int k = ks * 8;
            uint32_t a[2][4], b[8][2];
#pragma unroll
            for (int mt = 0; mt < 2; mt++) {
                ldsm_x4(a[mt], abase + (uint32_t)(mt * 16 * SA * 4 + ks * 32));
                a[mt][0] = rna13(a[mt][0]); a[mt][1] = rna13(a[mt][1]);
                a[mt][2] = rna13(a[mt][2]); a[mt][3] = rna13(a[mt][3]);
            }
#pragma unroll
            for (int nt = 0; nt < 8; nt++) {
                int cc = cb + nt * 8;
                b[nt][0] = rna13(Bu[(k + tig) * SB + cc]);
                b[nt][1] = rna13(Bu[(k + tig + 4) * SB + cc]);
            }
#pragma unroll
            for (int mt = 0; mt < 2; mt++)
#pragma unroll
                for (int nt = 0; nt < 8; nt++)
                    mma_tf32(acc[mt][nt], a[mt], b[nt]);
        }
    }

#pragma unroll
    for (int mt = 0; mt < 2; mt++) {
        int r = mbase + wm * 32 + mt * 16 + gid;
#pragma unroll
        for (int nt = 0; nt < 8; nt++) {
            int c = ncol + wn * 64 + nt * 8 + 2 * tig;
            if (UP) {
                float2 ga = *(float2*)&g_hu[(size_t)r * HID + c];
                float2 gb = *(float2*)&g_hu[(size_t)(r + 8) * HID + c];
                float h0 = frna(ga.x * (1.f / (1.f + __expf(-ga.x))) * acc[mt][nt][0]);
                float h1 = frna(ga.y * (1.f / (1.f + __expf(-ga.y))) * acc[mt][nt][1]);
                float h2 = frna(gb.x * (1.f / (1.f + __expf(-gb.x))) * acc[mt][nt][2]);
                float h3 = frna(gb.y * (1.f / (1.f + __expf(-gb.y))) * acc[mt][nt][3]);
                *(float2*)&g_hg[(size_t)r * HID + c]       = make_float2(h0, h1);
                *(float2*)&g_hg[(size_t)(r + 8) * HID + c] = make_float2(h2, h3);
            } else {
                *(float2*)&g_hu[(size_t)r * HID + c] =
                    make_float2(acc[mt][nt][0], acc[mt][nt][1]);
                *(float2*)&g_hu[(size_t)(r + 8) * HID + c] =
                    make_float2(acc[mt][nt][2], acc[mt][nt][3]);
            }
        }
    }
}

__global__ __launch_bounds__(256) void k_g1gate(const float* __restrict__ x,
                                                const float* __restrict__ wg) {
    gemm1_body<0>(x, wg);
}
__global__ __launch_bounds__(256) void k_g1up(const float* __restrict__ x,
                                              const float* __restrict__ wu) {
    gemm1_body<1>(x, wu);
}

// ---------------- GEMM2: [Mpad,4096] x [4096,1024], atomic epilogue -------------
__global__ __launch_bounds__(256) void k_gemm2_mma(const float* __restrict__ w_down,
                                                   float* __restrict__ out) {
    extern __shared__ float sm[];
    int total = g_offpad[NEXP];
    int mbase = blockIdx.y * BM;
    if (mbase >= total) return;
    int e = 0;
#pragma unroll
    for (int i = 0; i < NEXP; i++) if (mbase >= g_offpad[i + 1]) e = i + 1;

    const float* W = w_down + (size_t)e * HID * DIM;
    int ncol = blockIdx.x * BN;

    int tid = threadIdx.x;
    uint32_t smb = smem_u32(sm);

    int arow0 = tid >> 3, akf = (tid & 7) * 4;
    uint32_t adst[4]; const float* asrc[4];
#pragma unroll
    for (int p = 0; p < 4; p++) {
        int row = arow0 + p * 32;
        adst[p] = (uint32_t)(row * SA + akf) * 4;
        asrc[p] = g_hg + (size_t)(mbase + row) * HID + akf;
    }
    int bkr0 = tid >> 5, bnf = (tid & 31) * 4;
    uint32_t bdst[4]; const float* bsrc[4];
#pragma unroll
    for (int p = 0; p < 4; p++) {
        int kr = bkr0 + p * 8;
        bdst[p] = (uint32_t)(ASTG + kr * SB + bnf) * 4;
        bsrc[p] = W + (size_t)kr * DIM + ncol + bnf;
    }

    int lane = tid & 31, gid = lane >> 2, tig = lane & 3;
    int wm = (tid >> 5) & 3, wn = tid >> 7;
    int cb = wn * 64 + gid;
    uint32_t aln = (uint32_t)(((wm * 32 + (lane & 15)) * SA + (lane >> 4) * 4) * 4);

    float acc[2][8][4];
#pragma unroll
    for (int mt = 0; mt < 2; mt++)
#pragma unroll
        for (int nt = 0; nt < 8; nt++)
#pragma unroll
            for (int q = 0; q < 4; q++) acc[mt][nt][q] = 0.f;

    const int NT = HID / BK;            // 128
#pragma unroll
    for (int t = 0; t < 2; t++) {
        uint32_t base = smb + t * STGB;
        int k0 = t * BK;
#pragma unroll
        for (int p = 0; p < 4; p++) cp16(base + adst[p], asrc[p] + k0, 16);
#pragma unroll
        for (int p = 0; p < 4; p++)
            cp16(base + bdst[p], bsrc[p] + (size_t)k0 * DIM, 16);
        CP_COMMIT();
    }

    for (int i = 0; i < NT; i++) {
        CP_WAIT1();
        __syncthreads();
        int t = i + 2;
        if (t < NT) {
            uint32_t base = smb + (t % 3) * STGB;
            int k0 = t * BK;
#pragma unroll
            for (int p = 0; p < 4; p++) cp16(base + adst[p], asrc[p] + k0, 16);
#pragma unroll
            for (int p = 0; p < 4; p++)
                cp16(base + bdst[p], bsrc[p] + (size_t)k0 * DIM, 16);
        }
        CP_COMMIT();

        uint32_t abase = smb + (uint32_t)(i % 3) * STGB + aln;
        const uint32_t* Bu = (const uint32_t*)(sm + (i % 3) * STGF) + ASTG;
#pragma unroll
        for (int ks = 0; ks < 4; ks++) {
            int k = ks * 8;
            uint32_t a[2][4], b[8][2];
#pragma unroll
            for (int mt = 0; mt < 2; mt++)
                ldsm_x4(a[mt], abase + (uint32_t)(mt * 16 * SA * 4 + ks * 32));
#pragma unroll
            for (int nt = 0; nt < 8; nt++) {
                int cc = cb + nt * 8;
                b[nt][0] = rna13(Bu[(k + tig) * SB + cc]);
                b[nt][1] = rna13(Bu[(k + tig + 4) * SB + cc]);
            }
#pragma unroll
            for (int mt = 0; mt < 2; mt++)
#pragma unroll
                for (int nt = 0; nt < 8; nt++)
                    mma_tf32(acc[mt][nt], a[mt], b[nt]);
        }
    }

#pragma unroll
    for (int mt = 0; mt < 2; mt++) {
        int slot = mbase + wm * 32 + mt * 16 + gid;
        int tok0 = g_perm[slot],     tok1 = g_perm[slot + 8];
        float w0 = g_permw[slot],    w1 = g_permw[slot + 8];
#pragma unroll
        for (int nt = 0; nt < 8; nt++) {
            int c = ncol + wn * 64 + nt * 8 + 2 * tig;
            if (tok0 >= 0) {
                float* op = out + (size_t)tok0 * DIM + c;
                atomicAdd(op,     w0 * acc[mt][nt][0]);
                atomicAdd(op + 1, w0 * acc[mt][nt][1]);
            }
            if (tok1 >= 0) {
                float* op = out + (size_t)tok1 * DIM + c;
                atomicAdd(op,     w1 * acc[mt][nt][2]);
                atomicAdd(op + 1, w1 * acc[mt][nt][3]);
            }
        }
    }
}

// ---------------- launch ----------------
extern "C" void kernel_launch(void* const* d_in, const int* in_sizes, int n_in,
                              void* d_out, int out_size) {
    const float* x      = (const float*)d_in[0];
    const float* gate_w = (const float*)d_in[1];
    const float* w_gate = (const float*)d_in[2];
    const float* w_up   = (const float*)d_in[3];
    const float* w_down = (const float*)d_in[4];
    float* out = (float*)d_out;

    cudaFuncSetAttribute(k_g1gate, cudaFuncAttributeMaxDynamicSharedMemorySize,
                         SMEM_DYN);
    cudaFuncSetAttribute(k_g1up, cudaFuncAttributeMaxDynamicSharedMemorySize,
                         SMEM_DYN);
    cudaFuncSetAttribute(k_gemm2_mma, cudaFuncAttributeMaxDynamicSharedMemorySize,
                         SMEM_DYN);

    k_init<<<MAXPAD / 256, 256>>>();
    k_zero_out<<<2048, 256>>>((float4*)out, (T_TOK * DIM) / 4);
    k_gate<<<T_TOK / 8, 256>>>(x, gate_w);
    k_offsets<<<1, 32>>>(out);
    k_scatter<<<(2 * T_TOK) / 256, 256>>>();

    k_g1gate<<<dim3(HID / BN, NMPAD), 256, SMEM_DYN>>>(x, w_gate);
    k_g1up<<<dim3(HID / BN, NMPAD), 256, SMEM_DYN>>>(x, w_up);
    k_gemm2_mma<<<dim3(DIM / BN, NMPAD), 256, SMEM_DYN>>>(w_down, out);
}